// round 9
// baseline (speedup 1.0000x reference)
#include <cuda_runtime.h>

// Problem constants (fixed by the reference setup)
#define NBATCH 32
#define NATOM 256
#define PAIRS_PB 15360
#define NN (NBATCH * PAIRS_PB)      // 491520 total pairs
#define TOTNATOM (NBATCH * NATOM)   // 8192
#define NWAVE 8
#define NSYM 10                     // symmetric channels: 1, x,y,z, xx,xy,xz,yy,yz,zz
#define NORBIT 128
#define NSUB 4                      // sub-bins (and sub-counters) per atom
#define CAPS 40                     // capacity per sub-bin (mean 15, sigma ~3.9)
#define APB 8                       // atoms per block (gather)
#define HSTRIDE 80                  // floats per (atom,half) slab: 10*8
#define PBATCH 4                    // pairs per thread in pair_kernel

// Per-(atom,sub) pair bins: record = {ux|sp(2 low bits), uy, uz, d} (16 B)
__device__ float4 g_rec[(size_t)TOTNATOM * NSUB * CAPS];   // 21 MB (L2-resident)
// Sub-counters laid out [sub][atom] so one atom's 4 counters sit in different
// L2 slices (32 KB apart) -> per-address atomic contention drops 4x.
__device__ int    g_cnt4[NSUB * TOTNATOM];                 // zero-init; gather resets
// Overflow fallback accumulator [atom][c(10)][w(8)]; gather re-zeroes on use
__device__ float4 g_S[TOTNATOM * (NSYM * NWAVE / 4)];      // 2.6 MB

__device__ __forceinline__ void red_add_v4(float4* ptr, float a, float b, float c, float d) {
    asm volatile("red.global.add.v4.f32 [%0], {%1, %2, %3, %4};"
                 :: "l"(ptr), "f"(a), "f"(b), "f"(c), "f"(d) : "memory");
}
__device__ __forceinline__ float ex2_approx(float x) {
    float r;
    asm("ex2.approx.f32 %0, %1;" : "=f"(r) : "f"(x));
    return r;
}
__device__ __forceinline__ float sel4(int s, float v0, float v1, float v2, float v3) {
    float lo = (s & 1) ? v1 : v0;
    float hi = (s & 1) ? v3 : v2;
    return (s & 2) ? hi : lo;
}

// ---------------------------------------------------------------------------
// Kernel 1: per-pair geometry + binning, 4 pairs/thread software-pipelined.
// Slot atomic goes to one of 4 per-atom sub-counters (sub = t&3), quartering
// the same-address serialization at the L2 atomic unit.
// ---------------------------------------------------------------------------
__global__ void __launch_bounds__(256) pair_kernel(
    const float* __restrict__ cart,        // (totnatom, 3)
    const int*   __restrict__ species,     // (totnatom,)
    const int*   __restrict__ atom_index,  // (2, NN) flattened
    const float* __restrict__ shifts,      // (NN, 3)
    const float* __restrict__ rs,          // (NTYPE, 8)
    const float* __restrict__ inta,        // (NTYPE, 8)
    const float* __restrict__ params)      // (NTYPE, 8)
{
    const int QT = NN / PBATCH;
    const int t  = blockIdx.x * blockDim.x + threadIdx.x;
    if (t >= QT) return;
    const int sub = t & 3;

    int pp[PBATCH], ii[PBATCH], jj[PBATCH], slot[PBATCH];

    // Phase A: index loads (coalesced in all 4 streams)
#pragma unroll
    for (int k = 0; k < PBATCH; k++) {
        int p = t + k * QT;
        int b = p / PAIRS_PB;
        pp[k] = p;
        ii[k] = __ldg(&atom_index[p])      + b * NATOM;
        jj[k] = __ldg(&atom_index[NN + p]) + b * NATOM;
    }

    // Phase B: fire all slot atomics (4 L2 round-trips overlap)
#pragma unroll
    for (int k = 0; k < PBATCH; k++)
        slot[k] = atomicAdd(&g_cnt4[sub * TOTNATOM + ii[k]], 1);

    // Phase C: geometry + species loads for all 4 pairs
    float dx[PBATCH], dy[PBATCH], dz[PBATCH];
    int sp[PBATCH];
#pragma unroll
    for (int k = 0; k < PBATCH; k++) {
        dx[k] = __ldg(&cart[3 * ii[k] + 0]) - __ldg(&cart[3 * jj[k] + 0]) + __ldg(&shifts[3 * pp[k] + 0]);
        dy[k] = __ldg(&cart[3 * ii[k] + 1]) - __ldg(&cart[3 * jj[k] + 1]) + __ldg(&shifts[3 * pp[k] + 1]);
        dz[k] = __ldg(&cart[3 * ii[k] + 2]) - __ldg(&cart[3 * jj[k] + 2]) + __ldg(&shifts[3 * pp[k] + 2]);
        sp[k] = __ldg(&species[jj[k]]);
    }

    // Phase D: compute + store
#pragma unroll
    for (int k = 0; k < PBATCH; k++) {
        float d2  = dx[k] * dx[k] + dy[k] * dy[k] + dz[k] * dz[k];
        float inv = rsqrtf(d2);
        float d   = d2 * inv;                 // |r|
        float ux = dx[k] * inv, uy = dy[k] * inv, uz = dz[k] * inv;

        if (slot[k] < CAPS) {
            // pack species into 2 low mantissa bits of ux (<=3 ulp perturbation)
            unsigned uxb = (__float_as_uint(ux) & ~3u) | (unsigned)sp[k];
            g_rec[((size_t)ii[k] * NSUB + sub) * CAPS + slot[k]] =
                make_float4(__uint_as_float(uxb), uy, uz, d);
        } else {
            // Overflow fallback (rare): exact red-atomic scatter
            float rc[NWAVE];
#pragma unroll
            for (int w = 0; w < NWAVE; w++) {
                float tt = d - __ldg(&rs[sp[k] * NWAVE + w]);
                rc[w] = __expf(__ldg(&inta[sp[k] * NWAVE + w]) * tt * tt) * __ldg(&params[sp[k] * NWAVE + w]);
            }
            float ang[NSYM] = {1.f, ux, uy, uz,
                               ux * ux, ux * uy, ux * uz, uy * uy, uy * uz, uz * uz};
            float4* Sa = g_S + (size_t)ii[k] * (NSYM * NWAVE / 4);
#pragma unroll
            for (int c = 0; c < NSYM; c++) {
                float a = ang[c];
                red_add_v4(&Sa[2 * c + 0], a * rc[0], a * rc[1], a * rc[2], a * rc[3]);
                red_add_v4(&Sa[2 * c + 1], a * rc[4], a * rc[5], a * rc[6], a * rc[7]);
            }
        }
    }
}

// ---------------------------------------------------------------------------
// Kernel 2: gather + hyper contraction. 8 atoms/block, 128 threads, grid 1024.
// Phase 1: 16 threads/atom = (half 0/1) x (w 0..7); half h scans sub-bins
// {2h, 2h+1}. Species tables live in REGISTERS (2-bit select), no LDS.
// Phase 2: combine halves in smem, folding sqrt(channel weight).
// Phase 3: thread owns orbit column m, loops 8 atoms.
// Also resets g_cnt4 (and g_S if overflow) for the next graph replay.
// ---------------------------------------------------------------------------
__global__ void __launch_bounds__(128) gather_kernel(
    const float* __restrict__ rs,      // (NTYPE, 8)
    const float* __restrict__ inta,    // (NTYPE, 8)
    const float* __restrict__ params,  // (NTYPE, 8)
    const float* __restrict__ hyper,   // (3, 8, 128)
    float* __restrict__ out)           // (totnatom, 128)
{
    const int tid  = threadIdx.x;
    const int la   = tid >> 4;         // local atom 0..7
    const int half = (tid >> 3) & 1;   // half 0 -> subs {0,1}, half 1 -> {2,3}
    const int w    = tid & 7;          // wave index 0..7
    const int a    = blockIdx.x * APB + la;

    __shared__ float Ssm[APB * 2 * HSTRIDE];             // 5 KB

    // Register-resident species tables for this w (4 species each)
    const float L2E = 1.4426950408889634f;
    const float R0 = __ldg(&rs[w]),          R1 = __ldg(&rs[8 + w]);
    const float R2 = __ldg(&rs[16 + w]),     R3 = __ldg(&rs[24 + w]);
    const float A0 = __ldg(&inta[w]) * L2E,  A1 = __ldg(&inta[8 + w]) * L2E;
    const float A2 = __ldg(&inta[16 + w]) * L2E, A3 = __ldg(&inta[24 + w]) * L2E;
    const float P0 = __ldg(&params[w]),      P1 = __ldg(&params[8 + w]);
    const float P2 = __ldg(&params[16 + w]), P3 = __ldg(&params[24 + w]);

    // ---- counts: read all 4 sub-counters, detect overflow, reset ----
    int cnt[NSUB];
#pragma unroll
    for (int s = 0; s < NSUB; s++) cnt[s] = g_cnt4[s * TOTNATOM + a];
    bool of = (cnt[0] > CAPS) | (cnt[1] > CAPS) | (cnt[2] > CAPS) | (cnt[3] > CAPS);
    if ((tid & 15) < NSUB) g_cnt4[(tid & 15) * TOTNATOM + a] = 0;   // reset

    float acc[NSYM];
    if (of && half == 0) {             // overflow init + re-zero (rare)
        float* gs = (float*)(g_S + (size_t)a * (NSYM * NWAVE / 4));
#pragma unroll
        for (int c = 0; c < NSYM; c++) {
            acc[c] = gs[c * NWAVE + w];
            gs[c * NWAVE + w] = 0.f;
        }
    } else {
#pragma unroll
        for (int c = 0; c < NSYM; c++) acc[c] = 0.f;
    }

    // ---- Phase 1: scan this half's two sub-bins ----
#pragma unroll
    for (int si = 0; si < 2; si++) {
        const int s  = half * 2 + si;
        const int nc = min(cnt[s], CAPS);
        const float4* rec = g_rec + ((size_t)a * NSUB + s) * CAPS;
#pragma unroll 2
        for (int p = 0; p < nc; p++) {
            float4 r = __ldg(&rec[p]);             // 8-lane broadcast
            unsigned uxb = __float_as_uint(r.x);
            int spc = (int)(uxb & 3u);
            float ux = __uint_as_float(uxb & ~3u);
            float t  = r.w - sel4(spc, R0, R1, R2, R3);
            float rc = ex2_approx(sel4(spc, A0, A1, A2, A3) * t * t)
                     * sel4(spc, P0, P1, P2, P3);

            acc[0] += rc;
            float tx = rc * ux, ty = rc * r.y, tz = rc * r.z;
            acc[1] += tx;       acc[2] += ty;       acc[3] += tz;
            acc[4] += tx * ux;  acc[5] += tx * r.y; acc[6] += tx * r.z;
            acc[7] += ty * r.y; acc[8] += ty * r.z; acc[9] += tz * r.z;
        }
    }

    // ---- Phase 2: stash halves, then combine with sqrt(weight) fold ----
#pragma unroll
    for (int c = 0; c < NSYM; c++)
        Ssm[(la * 2 + half) * HSTRIDE + c * NWAVE + w] = acc[c];
    __syncthreads();

    {
        // channel weights {1,1,1,1,1,2,2,1,2,1} -> sqrt folded into S
        const float SQ2 = 1.41421356237309515f;
        const float scl[NSYM] = {1.f, 1.f, 1.f, 1.f, 1.f, SQ2, SQ2, 1.f, SQ2, 1.f};
#pragma unroll
        for (int idx = tid; idx < APB * HSTRIDE; idx += 128) {
            int at  = idx / HSTRIDE;
            int cw  = idx - at * HSTRIDE;
            float v = Ssm[(at * 2) * HSTRIDE + cw] + Ssm[(at * 2 + 1) * HSTRIDE + cw];
            Ssm[(at * 2) * HSTRIDE + cw] = v * scl[cw >> 3];
        }
    }
    __syncthreads();

    // ---- Phase 3: hyper contraction; thread = orbit column m ----
    const int m = tid;
    float h[3][NWAVE];
#pragma unroll
    for (int k = 0; k < 3; k++)
#pragma unroll
        for (int v = 0; v < NWAVE; v++)
            h[k][v] = __ldg(&hyper[(k * NWAVE + v) * NORBIT + m]);

    const int k_of[NSYM] = {0, 1, 1, 1, 2, 2, 2, 2, 2, 2};

#pragma unroll 1
    for (int la2 = 0; la2 < APB; la2++) {
        const float* S = Ssm + (la2 * 2) * HSTRIDE;
        float dens = 0.f;
#pragma unroll
        for (int c = 0; c < NSYM; c++) {
            const int k = k_of[c];
            float4 s0 = *(const float4*)(S + c * NWAVE);
            float4 s1 = *(const float4*)(S + c * NWAVE + 4);
            float t = s0.x * h[k][0] + s0.y * h[k][1] + s0.z * h[k][2] + s0.w * h[k][3]
                    + s1.x * h[k][4] + s1.y * h[k][5] + s1.z * h[k][6] + s1.w * h[k][7];
            dens += t * t;
        }
        out[(blockIdx.x * APB + la2) * NORBIT + m] = dens;
    }
}

// ---------------------------------------------------------------------------
// Launch (2 kernels; counters self-reset inside gather)
// ---------------------------------------------------------------------------
extern "C" void kernel_launch(void* const* d_in, const int* in_sizes, int n_in,
                              void* d_out, int out_size) {
    const float* cart       = (const float*)d_in[0];
    // d_in[1] = numatoms (unused by the reference math)
    const int*   species    = (const int*)  d_in[2];
    const int*   atom_index = (const int*)  d_in[3];
    const float* shifts     = (const float*)d_in[4];
    const float* rs         = (const float*)d_in[5];
    const float* inta       = (const float*)d_in[6];
    const float* params     = (const float*)d_in[7];
    const float* hyper      = (const float*)d_in[8];
    float* out = (float*)d_out;

    pair_kernel<<<(NN / PBATCH + 255) / 256, 256>>>(cart, species, atom_index, shifts,
                                                    rs, inta, params);
    gather_kernel<<<TOTNATOM / APB, 128>>>(rs, inta, params, hyper, out);
}

// round 10
// speedup vs baseline: 1.0633x; 1.0633x over previous
#include <cuda_runtime.h>

// Problem constants (fixed by the reference setup)
#define NBATCH 32
#define NATOM 256
#define PAIRS_PB 15360
#define NN (NBATCH * PAIRS_PB)      // 491520 total pairs
#define TOTNATOM (NBATCH * NATOM)   // 8192
#define NWAVE 8
#define NSYM 10                     // symmetric channels: 1, x,y,z, xx,xy,xz,yy,yz,zz
#define NORBIT 128
#define CAP 96                      // bin capacity (mean 60, sigma 7.7)
#define APB 8                       // atoms per block (gather)
#define HSTRIDE 80                  // floats per (atom,half) slab: 10*8
#define PBATCH 4                    // pairs per thread in pair_kernel

// Per-atom pair bins: record = {ux|sp(2 low bits), uy, uz, d} = 1 float4 (16 B)
__device__ float4 g_rec[(size_t)TOTNATOM * CAP];       // 12.6 MB (L2-resident)
__device__ int    g_cnt[TOTNATOM];                     // zero-init (.bss); gather resets
// Overflow fallback accumulator [atom][c(10)][w(8)]; gather re-zeroes on use
__device__ float4 g_S[TOTNATOM * (NSYM * NWAVE / 4)];  // 2.6 MB

__device__ __forceinline__ void red_add_v4(float4* ptr, float a, float b, float c, float d) {
    asm volatile("red.global.add.v4.f32 [%0], {%1, %2, %3, %4};"
                 :: "l"(ptr), "f"(a), "f"(b), "f"(c), "f"(d) : "memory");
}
__device__ __forceinline__ float ex2_approx(float x) {
    float r;
    asm("ex2.approx.f32 %0, %1;" : "=f"(r) : "f"(x));
    return r;
}
#define MUL_F32X2(d, a, b) \
    asm("mul.rn.f32x2 %0, %1, %2;" : "=l"(d) : "l"(a), "l"(b))
#define FMA_F32X2(d, a, b, c) \
    asm("fma.rn.f32x2 %0, %1, %2, %3;" : "=l"(d) : "l"(a), "l"(b), "l"(c))
#define PACK2(d, lo, hi) \
    asm("mov.b64 %0, {%1, %2};" : "=l"(d) : "f"(lo), "f"(hi))
#define UNPACK2(lo, hi, s) \
    asm("mov.b64 {%0, %1}, %2;" : "=f"(lo), "=f"(hi) : "l"(s))

// ---------------------------------------------------------------------------
// Kernel 1: per-pair geometry + binning, 4 pairs/thread, with batch-resident
// smem caches for cart (float4) + species. All 7 random per-pair gathers
// become LDS; only the slot atomic + the 16B record store stay global-random.
// Each of the 4 pair-streams of a 256-thread block lies in ONE batch
// (15360 = 60*256, QT = 8*15360), so 4 batch caches cover the block.
// ---------------------------------------------------------------------------
__global__ void __launch_bounds__(256) pair_kernel(
    const float* __restrict__ cart,        // (totnatom, 3)
    const int*   __restrict__ species,     // (totnatom,)
    const int*   __restrict__ atom_index,  // (2, NN) flattened
    const float* __restrict__ shifts,      // (NN, 3)
    const float* __restrict__ rs,          // (NTYPE, 8)
    const float* __restrict__ inta,        // (NTYPE, 8)
    const float* __restrict__ params)      // (NTYPE, 8)
{
    const int QT  = NN / PBATCH;           // 122880
    const int tid = threadIdx.x;
    const int p0  = blockIdx.x * 256;
    const int t   = p0 + tid;

    __shared__ float4 Csm[PBATCH][NATOM];  // 16 KB
    __shared__ int    Ssp[PBATCH][NATOM];  // 4 KB

    int bk[PBATCH];
#pragma unroll
    for (int k = 0; k < PBATCH; k++) {
        bk[k] = (p0 + k * QT) / PAIRS_PB;  // batch of stream k (block-constant)
        const float* cr = cart + (size_t)(bk[k] * NATOM + tid) * 3;
        Csm[k][tid] = make_float4(__ldg(cr), __ldg(cr + 1), __ldg(cr + 2), 0.f);
        Ssp[k][tid] = __ldg(&species[bk[k] * NATOM + tid]);
    }
    __syncthreads();

    int pp[PBATCH], il[PBATCH], jl[PBATCH], slot[PBATCH];

    // Phase A: index loads (coalesced in all 4 streams)
#pragma unroll
    for (int k = 0; k < PBATCH; k++) {
        int p = t + k * QT;
        pp[k] = p;
        il[k] = __ldg(&atom_index[p]);          // local (0..255)
        jl[k] = __ldg(&atom_index[NN + p]);
    }

    // Phase B: fire all slot atomics (4 L2 round-trips overlap)
#pragma unroll
    for (int k = 0; k < PBATCH; k++)
        slot[k] = atomicAdd(&g_cnt[bk[k] * NATOM + il[k]], 1);

    // Phase C: geometry from smem + coalesced shift loads
    float dx[PBATCH], dy[PBATCH], dz[PBATCH];
    int sp[PBATCH];
#pragma unroll
    for (int k = 0; k < PBATCH; k++) {
        float4 ci = Csm[k][il[k]];
        float4 cj = Csm[k][jl[k]];
        dx[k] = ci.x - cj.x + __ldg(&shifts[3 * pp[k] + 0]);
        dy[k] = ci.y - cj.y + __ldg(&shifts[3 * pp[k] + 1]);
        dz[k] = ci.z - cj.z + __ldg(&shifts[3 * pp[k] + 2]);
        sp[k] = Ssp[k][jl[k]];
    }

    // Phase D: compute + store
#pragma unroll
    for (int k = 0; k < PBATCH; k++) {
        float d2  = dx[k] * dx[k] + dy[k] * dy[k] + dz[k] * dz[k];
        float inv = rsqrtf(d2);
        float d   = d2 * inv;                 // |r|
        float ux = dx[k] * inv, uy = dy[k] * inv, uz = dz[k] * inv;
        int ig = bk[k] * NATOM + il[k];       // global center atom

        if (slot[k] < CAP) {
            // pack species into 2 low mantissa bits of ux (<=3 ulp perturbation)
            unsigned uxb = (__float_as_uint(ux) & ~3u) | (unsigned)sp[k];
            g_rec[(size_t)ig * CAP + slot[k]] = make_float4(__uint_as_float(uxb), uy, uz, d);
        } else {
            // Overflow fallback (expected never taken): exact red-atomic scatter
            float rc[NWAVE];
#pragma unroll
            for (int w = 0; w < NWAVE; w++) {
                float tt = d - __ldg(&rs[sp[k] * NWAVE + w]);
                rc[w] = __expf(__ldg(&inta[sp[k] * NWAVE + w]) * tt * tt) * __ldg(&params[sp[k] * NWAVE + w]);
            }
            float ang[NSYM] = {1.f, ux, uy, uz,
                               ux * ux, ux * uy, ux * uz, uy * uy, uy * uz, uz * uz};
            float4* Sa = g_S + (size_t)ig * (NSYM * NWAVE / 4);
#pragma unroll
            for (int c = 0; c < NSYM; c++) {
                float a = ang[c];
                red_add_v4(&Sa[2 * c + 0], a * rc[0], a * rc[1], a * rc[2], a * rc[3]);
                red_add_v4(&Sa[2 * c + 1], a * rc[4], a * rc[5], a * rc[6], a * rc[7]);
            }
        }
    }
}

// ---------------------------------------------------------------------------
// Kernel 2: gather + hyper contraction. 8 atoms/block, 128 threads, grid 1024.
// Phase 1: 16 threads/atom = (half 0/1) x (w 0..7); interleaved bin halves
// (R3-proven shape, LDS species tables).
// Phase 2: combine halves into PACKED atom-pair layout {atom2p, atom2p+1}.
// Phase 3: packed fma.rn.f32x2 hyper contraction over 4 atom-pairs.
// Also resets g_cnt (and g_S if overflow) for the next graph replay.
// ---------------------------------------------------------------------------
__global__ void __launch_bounds__(128) gather_kernel(
    const float* __restrict__ rs,      // (NTYPE, 8)
    const float* __restrict__ inta,    // (NTYPE, 8)
    const float* __restrict__ params,  // (NTYPE, 8)
    const float* __restrict__ hyper,   // (3, 8, 128)
    float* __restrict__ out)           // (totnatom, 128)
{
    const int tid  = threadIdx.x;
    const int la   = tid >> 4;         // local atom 0..7
    const int half = (tid >> 3) & 1;   // bin half 0/1
    const int w    = tid & 7;          // wave index 0..7
    const int a    = blockIdx.x * APB + la;

    __shared__ float Trs[32], TA[32], TP[32];               // species tables
    __shared__ float Ssm[APB * 2 * HSTRIDE];                // 5 KB (halves)
    __shared__ __align__(16) float2 Pk[APB / 2][NSYM * NWAVE];  // 2.5 KB packed

    if (tid < 32) {
        Trs[tid] = __ldg(&rs[tid]);
        TA[tid]  = __ldg(&inta[tid]) * 1.4426950408889634f;   // fold log2(e)
        TP[tid]  = __ldg(&params[tid]);
    }
    __syncthreads();

    // ---- Phase 1: per-(atom, half, w) symmetric moment accumulation ----
    const int n  = g_cnt[a];
    const int nc = min(n, CAP);
    if ((tid & 15) == 0) g_cnt[a] = 0;     // reset for next replay

    float acc[NSYM];
    if (n > CAP && half == 0) {            // overflow init + re-zero (expected never)
        float* gs = (float*)(g_S + (size_t)a * (NSYM * NWAVE / 4));
#pragma unroll
        for (int c = 0; c < NSYM; c++) {
            acc[c] = gs[c * NWAVE + w];
            gs[c * NWAVE + w] = 0.f;
        }
    } else {
#pragma unroll
        for (int c = 0; c < NSYM; c++) acc[c] = 0.f;
    }

    const float4* rec = g_rec + (size_t)a * CAP;
#pragma unroll 4
    for (int p = half; p < nc; p += 2) {
        float4 r = __ldg(&rec[p]);                 // broadcast across the 8 w-threads
        unsigned uxb = __float_as_uint(r.x);
        int sp8 = (int)(uxb & 3u) * NWAVE + w;
        float ux = __uint_as_float(uxb & ~3u);
        float t  = r.w - Trs[sp8];
        float rc = ex2_approx(TA[sp8] * t * t) * TP[sp8];

        acc[0] += rc;
        float tx = rc * ux, ty = rc * r.y, tz = rc * r.z;
        acc[1] += tx;       acc[2] += ty;       acc[3] += tz;
        acc[4] += tx * ux;  acc[5] += tx * r.y; acc[6] += tx * r.z;
        acc[7] += ty * r.y; acc[8] += ty * r.z; acc[9] += tz * r.z;
    }

    // ---- Phase 2: stash halves, then combine into packed pair layout ----
#pragma unroll
    for (int c = 0; c < NSYM; c++)
        Ssm[(la * 2 + half) * HSTRIDE + c * NWAVE + w] = acc[c];
    __syncthreads();

    {
        // channel weights {1,1,1,1,1,2,2,1,2,1} -> sqrt folded into S
        const float SQ2 = 1.41421356237309515f;
        const float scl[NSYM] = {1.f, 1.f, 1.f, 1.f, 1.f, SQ2, SQ2, 1.f, SQ2, 1.f};
#pragma unroll
        for (int idx = tid; idx < APB * HSTRIDE; idx += 128) {
            int at = idx / HSTRIDE;
            int cw = idx - at * HSTRIDE;
            float v = Ssm[(at * 2) * HSTRIDE + cw] + Ssm[(at * 2 + 1) * HSTRIDE + cw];
            ((float*)&Pk[at >> 1][cw])[at & 1] = v * scl[cw >> 3];
        }
    }
    __syncthreads();

    // ---- Phase 3: packed f32x2 hyper contraction; thread = orbit column m ----
    const int m = tid;
    unsigned long long hp[3][NWAVE];       // h replicated into both packed halves
#pragma unroll
    for (int k = 0; k < 3; k++)
#pragma unroll
        for (int v = 0; v < NWAVE; v++) {
            float hv = __ldg(&hyper[(k * NWAVE + v) * NORBIT + m]);
            PACK2(hp[k][v], hv, hv);
        }

    const int k_of[NSYM] = {0, 1, 1, 1, 2, 2, 2, 2, 2, 2};

#pragma unroll 1
    for (int pr = 0; pr < APB / 2; pr++) {
        const ulonglong2* S2 = (const ulonglong2*)Pk[pr];
        unsigned long long dens;
        PACK2(dens, 0.f, 0.f);
#pragma unroll
        for (int c = 0; c < NSYM; c++) {
            const int k = k_of[c];
            ulonglong2 q0 = S2[c * 4 + 0];   // packed pairs for w=0,1
            ulonglong2 q1 = S2[c * 4 + 1];   // w=2,3
            ulonglong2 q2 = S2[c * 4 + 2];   // w=4,5
            ulonglong2 q3 = S2[c * 4 + 3];   // w=6,7
            unsigned long long tp;
            MUL_F32X2(tp, q0.x, hp[k][0]);
            FMA_F32X2(tp, q0.y, hp[k][1], tp);
            FMA_F32X2(tp, q1.x, hp[k][2], tp);
            FMA_F32X2(tp, q1.y, hp[k][3], tp);
            FMA_F32X2(tp, q2.x, hp[k][4], tp);
            FMA_F32X2(tp, q2.y, hp[k][5], tp);
            FMA_F32X2(tp, q3.x, hp[k][6], tp);
            FMA_F32X2(tp, q3.y, hp[k][7], tp);
            FMA_F32X2(dens, tp, tp, dens);
        }
        float d0, d1;
        UNPACK2(d0, d1, dens);
        const int a0 = blockIdx.x * APB + 2 * pr;
        out[a0 * NORBIT + m]       = d0;
        out[(a0 + 1) * NORBIT + m] = d1;
    }
}

// ---------------------------------------------------------------------------
// Launch (2 kernels; counters self-reset inside gather)
// ---------------------------------------------------------------------------
extern "C" void kernel_launch(void* const* d_in, const int* in_sizes, int n_in,
                              void* d_out, int out_size) {
    const float* cart       = (const float*)d_in[0];
    // d_in[1] = numatoms (unused by the reference math)
    const int*   species    = (const int*)  d_in[2];
    const int*   atom_index = (const int*)  d_in[3];
    const float* shifts     = (const float*)d_in[4];
    const float* rs         = (const float*)d_in[5];
    const float* inta       = (const float*)d_in[6];
    const float* params     = (const float*)d_in[7];
    const float* hyper      = (const float*)d_in[8];
    float* out = (float*)d_out;

    pair_kernel<<<NN / PBATCH / 256, 256>>>(cart, species, atom_index, shifts,
                                            rs, inta, params);
    gather_kernel<<<TOTNATOM / APB, 128>>>(rs, inta, params, hyper, out);
}